// round 16
// baseline (speedup 1.0000x reference)
#include <cuda_runtime.h>
#include <cuda_fp16.h>
#include <cstdint>

#define BSZ 32
#define NPT 1024
#define NN (BSZ*NPT)      /* 32768 */
#define TOT (2*NN)        /* 65536 */

#define THRESH 0.1f
#define ENT_WT 1e-4

typedef unsigned long long ull;

// ------------------------- scratch (device globals; no mallocs) -------------
__device__ uint32_t g_E[2u*BSZ*NPT*256];     // 64 MiB: exp(A) as e4m3, 4 per u32
__device__ uint32_t g_ScP[2u*BSZ*64*512];    // 8 MiB: f16x2 column partial Sc
__device__ uint32_t g_CP [2u*BSZ*64*512];    // 8 MiB: f16x2 column partial C
__device__ float  g_Sr[TOT];
__device__ float  g_Tr[TOT];
__device__ float  g_invSr[TOT];
__device__ float4 g_U4[TOT];
__device__ float  g_ssq1[BSZ], g_ssq2[BSZ], g_dot[BSZ];
__device__ float  g_T12[BSZ*12], g_T21[BSZ*12];
__device__ float4 g_pin[TOT];   // mat0: p1in2, mat1: p2in1  (w = |p|^2)
__device__ float4 g_pto[TOT];   // mat0: p1to2, mat1: p2to1  (w = |p|^2)
__device__ double g_acc[6];     // 0 cham, 1 corr, 2 ent2, 3 entG, 4 colterm

// ------------------------- helpers ------------------------------------------
__device__ __forceinline__ float wsum(float v) {
#pragma unroll
    for (int o = 16; o; o >>= 1) v += __shfl_down_sync(0xffffffffu, v, o);
    return v;
}

__device__ __forceinline__ float block_sum(float v, float* sm) {
    int lane = threadIdx.x & 31, w = threadIdx.x >> 5;
    v = wsum(v);
    if (lane == 0) sm[w] = v;
    __syncthreads();
    int nw = (blockDim.x + 31) >> 5;
    v = (threadIdx.x < nw) ? sm[threadIdx.x] : 0.f;
    if (w == 0) v = wsum(v);
    return v;
}

// packed f32x2 helpers
__device__ __forceinline__ ull pk2(float a, float b) {
    ull r;
    asm("mov.b64 %0, {%1,%2};" : "=l"(r) : "f"(a), "f"(b));
    return r;
}
__device__ __forceinline__ void upk2(ull v, float& a, float& b) {
    asm("mov.b64 {%0,%1}, %2;" : "=f"(a), "=f"(b) : "l"(v));
}
__device__ __forceinline__ ull mul2(ull a, ull b) {
    ull d;
    asm("mul.rn.f32x2 %0, %1, %2;" : "=l"(d) : "l"(a), "l"(b));
    return d;
}
__device__ __forceinline__ ull add2(ull a, ull b) {
    ull d;
    asm("add.rn.f32x2 %0, %1, %2;" : "=l"(d) : "l"(a), "l"(b));
    return d;
}
__device__ __forceinline__ ull fma2(ull a, ull b, ull c) {
    ull d;
    asm("fma.rn.f32x2 %0, %1, %2, %3;" : "=l"(d) : "l"(a), "l"(b), "l"(c));
    return d;
}
__device__ __forceinline__ float ex2f(float x) {
    float r; asm("ex2.approx.f32 %0, %1;" : "=f"(r) : "f"(x)); return r;
}
__device__ __forceinline__ float sum2(ull v) {
    float a, b; upk2(v, a, b); return a + b;
}

// fp8 e4m3 pack/unpack
__device__ __forceinline__ uint32_t pack_e4m3x4(float f0, float f1, float f2, float f3) {
    uint32_t r;
    asm("{\n\t.reg .b16 lo, hi;\n\t"
        "cvt.rn.satfinite.e4m3x2.f32 lo, %2, %1;\n\t"
        "cvt.rn.satfinite.e4m3x2.f32 hi, %4, %3;\n\t"
        "mov.b32 %0, {lo, hi};\n\t}"
        : "=r"(r) : "f"(f0), "f"(f1), "f"(f2), "f"(f3));
    return r;
}
__device__ __forceinline__ void unpack_e4m3x4(uint32_t v, uint32_t& h01, uint32_t& h23) {
    asm("{\n\t.reg .b16 lo, hi;\n\t"
        "mov.b32 {lo, hi}, %2;\n\t"
        "cvt.rn.f16x2.e4m3x2 %0, lo;\n\t"
        "cvt.rn.f16x2.e4m3x2 %1, hi;\n\t}"
        : "=r"(h01), "=r"(h23) : "r"(v));
}
__device__ __forceinline__ uint32_t hadd2u(uint32_t a, uint32_t b) {
    uint32_t d; asm("add.rn.f16x2 %0, %1, %2;" : "=r"(d) : "r"(a), "r"(b)); return d;
}
__device__ __forceinline__ uint32_t hfma2u(uint32_t a, uint32_t b, uint32_t c) {
    uint32_t d; asm("fma.rn.f16x2 %0, %1, %2, %3;" : "=r"(d) : "r"(a), "r"(b), "r"(c)); return d;
}
__device__ __forceinline__ uint32_t bcast_h2(float w) {
    uint32_t d;
    asm("{\n\t.reg .b16 h;\n\tcvt.rn.f16.f32 h, %1;\n\tmov.b32 %0, {h, h};\n\t}"
        : "=r"(d) : "f"(w));
    return d;
}
__device__ __forceinline__ void h2_to_f2(uint32_t v, float& a, float& b) {
    asm("{\n\t.reg .b16 lo, hi;\n\tmov.b32 {lo, hi}, %2;\n\t"
        "cvt.f32.f16 %0, lo;\n\tcvt.f32.f16 %1, hi;\n\t}"
        : "=f"(a), "=f"(b) : "r"(v));
}

// ------------------------- setup: init + pose (one launch) --------------------
__global__ void k_setup(const float* __restrict__ scale,
                        const float* __restrict__ rot,
                        const float* __restrict__ trans) {
    int i = threadIdx.x;   // 64 threads
    if (i >= 32 && i < 38) g_acc[i - 32] = 0.0;
    if (i >= BSZ) return;
    g_ssq1[i] = 0.f; g_ssq2[i] = 0.f; g_dot[i] = 0.f;

    int b = i;
    float s = scale[b];
    float m[9];
#pragma unroll
    for (int k = 0; k < 9; k++) m[k] = s * rot[b*9 + k];
    float t0 = trans[b*3+0], t1 = trans[b*3+1], t2 = trans[b*3+2];

    float* T = g_T12 + b*12;
    T[0]=m[0]; T[1]=m[1]; T[2]=m[2];  T[3]=t0;
    T[4]=m[3]; T[5]=m[4]; T[6]=m[5];  T[7]=t1;
    T[8]=m[6]; T[9]=m[7]; T[10]=m[8]; T[11]=t2;

    float c00=(m[4]*m[8]-m[5]*m[7]), c01=(m[2]*m[7]-m[1]*m[8]), c02=(m[1]*m[5]-m[2]*m[4]);
    float c10=(m[5]*m[6]-m[3]*m[8]), c11=(m[0]*m[8]-m[2]*m[6]), c12=(m[2]*m[3]-m[0]*m[5]);
    float c20=(m[3]*m[7]-m[4]*m[6]), c21=(m[1]*m[6]-m[0]*m[7]), c22=(m[0]*m[4]-m[1]*m[3]);
    float det = m[0]*c00 + m[1]*c10 + m[2]*c20;
    float id = 1.f/det;
    float i00=c00*id,i01=c01*id,i02=c02*id;
    float i10=c10*id,i11=c11*id,i12=c12*id;
    float i20=c20*id,i21=c21*id,i22=c22*id;
    float u0 = -(i00*t0 + i01*t1 + i02*t2);
    float u1 = -(i10*t0 + i11*t1 + i12*t2);
    float u2 = -(i20*t0 + i21*t1 + i22*t2);
    float* V = g_T21 + b*12;
    V[0]=i00; V[1]=i01; V[2]=i02;  V[3]=u0;
    V[4]=i10; V[5]=i11; V[6]=i12;  V[7]=u1;
    V[8]=i20; V[9]=i21; V[10]=i22; V[11]=u2;
}

// ------------------------- pass 1 (round-10 proven: packed f32x2, 1 row/warp) -
__global__ __launch_bounds__(256, 4)
void k_pass1(const float* __restrict__ A1, const float* __restrict__ A2,
             const float* __restrict__ P1, const float* __restrict__ P2) {
    __shared__ ull s1x[NPT/2], s1y[NPT/2], s1z[NPT/2];
    __shared__ ull s2x[NPT/2], s2y[NPT/2], s2z[NPT/2];
    __shared__ float rsm[32];

    const int b  = blockIdx.x;
    const int rb = blockIdx.y;
    const int tid = threadIdx.x;
    const int warp = tid >> 5, lane = tid & 31;

    const float* P1g = P1 + (size_t)b*NPT*3;
    const float* P2g = P2 + (size_t)b*NPT*3;
    for (int i = tid; i < NPT/2; i += 256) {
        const float* c1 = P1g + 6*i;
        s1x[i] = pk2(c1[0], c1[3]);
        s1y[i] = pk2(c1[1], c1[4]);
        s1z[i] = pk2(c1[2], c1[5]);
        const float* c2 = P2g + 6*i;
        s2x[i] = pk2(c2[0], c2[3]);
        s2y[i] = pk2(c2[1], c2[4]);
        s2z[i] = pk2(c2[2], c2[5]);
    }
    __syncthreads();

    const int row = rb*8 + warp;
    const float* A1r = A1 + ((size_t)b << 20) + ((size_t)row << 10);
    const float* A2r = A2 + ((size_t)b << 20) + ((size_t)row << 10);
    uint32_t* E1r = g_E + ((size_t)b << 18) + row*256;
    uint32_t* E2r = g_E + ((size_t)(BSZ + b) << 18) + row*256;

    const ull L2E = pk2(1.4426950408889634f, 1.4426950408889634f);

    ull sP1=0, tP1=0, uxP1=0, uyP1=0, uzP1=0;
    ull sP2=0, tP2=0, uxP2=0, uyP2=0, uzP2=0;
    ull ssP1=0, ssP2=0, dpP=0;

#pragma unroll
    for (int c = 0; c < 8; c++) {
        const int col = c*128 + lane*4;
        const float4 a1 = __ldcs((const float4*)&A1r[col]);
        const float4 a2 = __ldcs((const float4*)&A2r[col]);
        const ulonglong2 q2x = *(const ulonglong2*)&s2x[col >> 1];
        const ulonglong2 q2y = *(const ulonglong2*)&s2y[col >> 1];
        const ulonglong2 q2z = *(const ulonglong2*)&s2z[col >> 1];
        const ulonglong2 q1x = *(const ulonglong2*)&s1x[col >> 1];
        const ulonglong2 q1y = *(const ulonglong2*)&s1y[col >> 1];
        const ulonglong2 q1z = *(const ulonglong2*)&s1z[col >> 1];

        {
            ull a01 = pk2(a1.x, a1.y), a23 = pk2(a1.z, a1.w);
            ull x01 = mul2(a01, L2E),  x23 = mul2(a23, L2E);
            float f0, f1, f2, f3;
            upk2(x01, f0, f1); upk2(x23, f2, f3);
            float e0 = ex2f(f0), e1 = ex2f(f1), e2 = ex2f(f2), e3 = ex2f(f3);
            ull e01 = pk2(e0, e1), e23 = pk2(e2, e3);
            sP1 = add2(sP1, e01);      sP1 = add2(sP1, e23);
            tP1 = fma2(e01, a01, tP1); tP1 = fma2(e23, a23, tP1);
            uxP1 = fma2(e01, q2x.x, uxP1); uxP1 = fma2(e23, q2x.y, uxP1);
            uyP1 = fma2(e01, q2y.x, uyP1); uyP1 = fma2(e23, q2y.y, uyP1);
            uzP1 = fma2(e01, q2z.x, uzP1); uzP1 = fma2(e23, q2z.y, uzP1);
            ssP1 = fma2(a01, a01, ssP1);   ssP1 = fma2(a23, a23, ssP1);
            E1r[col >> 2] = pack_e4m3x4(e0, e1, e2, e3);

            ull b01 = pk2(a2.x, a2.y), b23 = pk2(a2.z, a2.w);
            dpP = fma2(a01, b01, dpP); dpP = fma2(a23, b23, dpP);
            ssP2 = fma2(b01, b01, ssP2);   ssP2 = fma2(b23, b23, ssP2);

            ull y01 = mul2(b01, L2E), y23 = mul2(b23, L2E);
            float g0, g1, g2, g3;
            upk2(y01, g0, g1); upk2(y23, g2, g3);
            float h0 = ex2f(g0), h1 = ex2f(g1), h2 = ex2f(g2), h3 = ex2f(g3);
            ull h01 = pk2(h0, h1), h23 = pk2(h2, h3);
            sP2 = add2(sP2, h01);      sP2 = add2(sP2, h23);
            tP2 = fma2(h01, b01, tP2); tP2 = fma2(h23, b23, tP2);
            uxP2 = fma2(h01, q1x.x, uxP2); uxP2 = fma2(h23, q1x.y, uxP2);
            uyP2 = fma2(h01, q1y.x, uyP2); uyP2 = fma2(h23, q1y.y, uyP2);
            uzP2 = fma2(h01, q1z.x, uzP2); uzP2 = fma2(h23, q1z.y, uzP2);
            E2r[col >> 2] = pack_e4m3x4(h0, h1, h2, h3);
        }
    }

    float s1 = wsum(sum2(sP1)),  t1 = wsum(sum2(tP1));
    float ux1 = wsum(sum2(uxP1)), uy1 = wsum(sum2(uyP1)), uz1 = wsum(sum2(uzP1));
    float s2v = wsum(sum2(sP2)),  t2v = wsum(sum2(tP2));
    float ux2 = wsum(sum2(uxP2)), uy2 = wsum(sum2(uyP2)), uz2 = wsum(sum2(uzP2));
    if (lane == 0) {
        size_t i1 = (size_t)b*NPT + row;
        size_t i2 = (size_t)NN + i1;
        g_Sr[i1] = s1; g_Tr[i1] = t1; g_invSr[i1] = 1.f/s1;
        g_U4[i1] = make_float4(ux1, uy1, uz1, 0.f);
        g_Sr[i2] = s2v; g_Tr[i2] = t2v; g_invSr[i2] = 1.f/s2v;
        g_U4[i2] = make_float4(ux2, uy2, uz2, 0.f);
    }

    float v = block_sum(sum2(ssP1), rsm);
    if (tid == 0) atomicAdd(&g_ssq1[b], v);
    __syncthreads();
    v = block_sum(sum2(ssP2), rsm);
    if (tid == 0) atomicAdd(&g_ssq2[b], v);
    __syncthreads();
    v = block_sum(sum2(dpP), rsm);
    if (tid == 0) atomicAdd(&g_dot[b], v);
}

// ------------------------- row finalize --------------------------------------
__global__ __launch_bounds__(256)
void k_rowfinal(const float* __restrict__ P1, const float* __restrict__ P2) {
    __shared__ float rsm[32];
    int idx = blockIdx.x * 256 + threadIdx.x;   // < 65536
    int mat = idx >> 15;
    int b   = (idx >> 10) & 31;
    int n   = idx & 1023;

    float sr  = g_Sr[idx];
    float isr = 1.f / sr;
    float gq  = g_Tr[idx] * isr;
    float e2p = __logf(sr) - gq;

    float4 u = g_U4[idx];
    float px = u.x*isr, py = u.y*isr, pz = u.z*isr;
    g_pin[idx] = make_float4(px, py, pz, px*px+py*py+pz*pz);

    const float* pts = mat ? P2 : P1;
    const float* T   = (mat ? g_T21 : g_T12) + b*12;
    float x0 = pts[((size_t)b*NPT+n)*3+0];
    float x1 = pts[((size_t)b*NPT+n)*3+1];
    float x2 = pts[((size_t)b*NPT+n)*3+2];
    float y0 = T[0]*x0 + T[1]*x1 + T[2]*x2 + T[3];
    float y1 = T[4]*x0 + T[5]*x1 + T[6]*x2 + T[7];
    float y2 = T[8]*x0 + T[9]*x1 + T[10]*x2 + T[11];
    g_pto[idx] = make_float4(y0, y1, y2, y0*y0+y1*y1+y2*y2);

#define HUBER(d) ((d) > THRESH ? (d) - 0.5f*THRESH : (d)*(d)*(0.5f/THRESH))
    float d0 = fabsf(px-y0), d1 = fabsf(py-y1), d2 = fabsf(pz-y2);
    float corr = HUBER(d0) + HUBER(d1) + HUBER(d2);
#undef HUBER

    float v = block_sum(e2p, rsm);
    if (threadIdx.x == 0) atomicAdd(&g_acc[2], (double)v);
    __syncthreads();
    v = block_sum(gq, rsm);
    if (threadIdx.x == 0) atomicAdd(&g_acc[3], (double)v);
    __syncthreads();
    v = block_sum(corr, rsm);
    if (threadIdx.x == 0) atomicAdd(&g_acc[1], (double)v);
}

// ------------------------- chamfer: 4 x/thread, lo/hi chains, y quartered ----
// grid 256: bx -> half(2) x b(32) x dir(2) x prob(2). 512 threads:
// g = tid>>7 selects y-quarter (128 pairs), t = tid&127 selects 4 x-points
// (x = half*512 + t + k*128). 8 independent min chains per thread.
__global__ __launch_bounds__(512)
void k_chamfer() {
    __shared__ ulonglong2 sYA[NPT/2];   // (x-pair, y-pair)
    __shared__ ulonglong2 sYB[NPT/2];   // (z-pair, w-pair)
    __shared__ float pm[4*512];         // [k][g*128+t] partial minima (8 KB)
    __shared__ float rsm[32];
    int bx = blockIdx.x;
    int half = bx & 1; int b = (bx >> 1) & 31; int dir = (bx >> 6) & 1; int prob = bx >> 7;
    size_t base = (size_t)(prob*BSZ + b) * NPT;
    const float4* X = dir ? (g_pin + base) : (g_pto + base);
    const float4* Y = dir ? (g_pto + base) : (g_pin + base);
    int tid = threadIdx.x;
    int g = tid >> 7, t = tid & 127;

    for (int i = tid; i < NPT/2; i += 512) {
        float4 y0 = Y[2*i], y1 = Y[2*i+1];
        sYA[i] = make_ulonglong2(pk2(y0.x, y1.x), pk2(y0.y, y1.y));
        sYB[i] = make_ulonglong2(pk2(y0.z, y1.z), pk2(y0.w, y1.w));
    }
    __syncthreads();

    const float4 x0 = X[half*512 + t];
    const float4 x1 = X[half*512 + t + 128];
    const float4 x2 = X[half*512 + t + 256];
    const float4 x3 = X[half*512 + t + 384];
    ull a0x = pk2(-2.f*x0.x, -2.f*x0.x), a0y = pk2(-2.f*x0.y, -2.f*x0.y), a0z = pk2(-2.f*x0.z, -2.f*x0.z);
    ull a1x = pk2(-2.f*x1.x, -2.f*x1.x), a1y = pk2(-2.f*x1.y, -2.f*x1.y), a1z = pk2(-2.f*x1.z, -2.f*x1.z);
    ull a2x = pk2(-2.f*x2.x, -2.f*x2.x), a2y = pk2(-2.f*x2.y, -2.f*x2.y), a2z = pk2(-2.f*x2.z, -2.f*x2.z);
    ull a3x = pk2(-2.f*x3.x, -2.f*x3.x), a3y = pk2(-2.f*x3.y, -2.f*x3.y), a3z = pk2(-2.f*x3.z, -2.f*x3.z);

    float mn0L = 1e30f, mn0H = 1e30f, mn1L = 1e30f, mn1H = 1e30f;
    float mn2L = 1e30f, mn2H = 1e30f, mn3L = 1e30f, mn3H = 1e30f;
    const int m0 = g*128;
#pragma unroll 4
    for (int m = m0; m < m0 + 128; m++) {
        const ulonglong2 A = sYA[m];
        const ulonglong2 B = sYB[m];
        ull v; float lo, hi;
        v = fma2(a0x, A.x, B.y); v = fma2(a0y, A.y, v); v = fma2(a0z, B.x, v);
        upk2(v, lo, hi); mn0L = fminf(mn0L, lo); mn0H = fminf(mn0H, hi);
        v = fma2(a1x, A.x, B.y); v = fma2(a1y, A.y, v); v = fma2(a1z, B.x, v);
        upk2(v, lo, hi); mn1L = fminf(mn1L, lo); mn1H = fminf(mn1H, hi);
        v = fma2(a2x, A.x, B.y); v = fma2(a2y, A.y, v); v = fma2(a2z, B.x, v);
        upk2(v, lo, hi); mn2L = fminf(mn2L, lo); mn2H = fminf(mn2H, hi);
        v = fma2(a3x, A.x, B.y); v = fma2(a3y, A.y, v); v = fma2(a3z, B.x, v);
        upk2(v, lo, hi); mn3L = fminf(mn3L, lo); mn3H = fminf(mn3H, hi);
    }
    pm[0*512 + g*128 + t] = fminf(mn0L, mn0H);
    pm[1*512 + g*128 + t] = fminf(mn1L, mn1H);
    pm[2*512 + g*128 + t] = fminf(mn2L, mn2H);
    pm[3*512 + g*128 + t] = fminf(mn3L, mn3H);
    __syncthreads();

    float dsum = 0.f;
    if (g == 0) {
        float f0 = fminf(fminf(pm[0*512 + t],       pm[0*512 + 128 + t]),
                         fminf(pm[0*512 + 256 + t], pm[0*512 + 384 + t]));
        float f1 = fminf(fminf(pm[1*512 + t],       pm[1*512 + 128 + t]),
                         fminf(pm[1*512 + 256 + t], pm[1*512 + 384 + t]));
        float f2 = fminf(fminf(pm[2*512 + t],       pm[2*512 + 128 + t]),
                         fminf(pm[2*512 + 256 + t], pm[2*512 + 384 + t]));
        float f3 = fminf(fminf(pm[3*512 + t],       pm[3*512 + 128 + t]),
                         fminf(pm[3*512 + 256 + t], pm[3*512 + 384 + t]));
        dsum = fmaxf(x0.w + f0, 0.f) + fmaxf(x1.w + f1, 0.f)
             + fmaxf(x2.w + f2, 0.f) + fmaxf(x3.w + f3, 0.f);
    }
    float v = block_sum(dsum, rsm);
    if (tid == 0) atomicAdd(&g_acc[0], (double)v);
}

// ------------------------- pass 2: fp8 column pass (atomic-free) --------------
__global__ __launch_bounds__(256)
void k_pass2() {
    __shared__ float isr[64];
    const int bx = blockIdx.x;
    const int chunk = bx & 15, b = (bx >> 4) & 31, mat = bx >> 9;
    const int tid = threadIdx.x;
    const int sub = tid >> 6, ct = tid & 63;

    if (tid < 64)
        isr[tid] = g_invSr[(size_t)(mat*BSZ + b)*NPT + chunk*64 + tid];
    __syncthreads();

    const int row0 = chunk*64 + sub*16;
    const uint4* Ep = (const uint4*)(g_E + ((size_t)(mat*BSZ + b) << 18) + row0*256) + ct;

    uint32_t sc[8], cc[8];
#pragma unroll
    for (int k = 0; k < 8; k++) { sc[k] = 0u; cc[k] = 0u; }

#pragma unroll 8
    for (int r = 0; r < 16; r++) {
        uint4 v = __ldcs(&Ep[(size_t)r*64]);
        uint32_t w2 = bcast_h2(isr[sub*16 + r]);
        uint32_t h0, h1;
        unpack_e4m3x4(v.x, h0, h1);
        sc[0]=hadd2u(sc[0],h0); cc[0]=hfma2u(h0,w2,cc[0]);
        sc[1]=hadd2u(sc[1],h1); cc[1]=hfma2u(h1,w2,cc[1]);
        unpack_e4m3x4(v.y, h0, h1);
        sc[2]=hadd2u(sc[2],h0); cc[2]=hfma2u(h0,w2,cc[2]);
        sc[3]=hadd2u(sc[3],h1); cc[3]=hfma2u(h1,w2,cc[3]);
        unpack_e4m3x4(v.z, h0, h1);
        sc[4]=hadd2u(sc[4],h0); cc[4]=hfma2u(h0,w2,cc[4]);
        sc[5]=hadd2u(sc[5],h1); cc[5]=hfma2u(h1,w2,cc[5]);
        unpack_e4m3x4(v.w, h0, h1);
        sc[6]=hadd2u(sc[6],h0); cc[6]=hfma2u(h0,w2,cc[6]);
        sc[7]=hadd2u(sc[7],h1); cc[7]=hfma2u(h1,w2,cc[7]);
    }

    const size_t o = (((size_t)(mat*BSZ + b)*64) + (size_t)(chunk*4 + sub))*512 + ct*8;
    *(uint4*)&g_ScP[o]     = make_uint4(sc[0], sc[1], sc[2], sc[3]);
    *(uint4*)&g_ScP[o + 4] = make_uint4(sc[4], sc[5], sc[6], sc[7]);
    *(uint4*)&g_CP[o]      = make_uint4(cc[0], cc[1], cc[2], cc[3]);
    *(uint4*)&g_CP[o + 4]  = make_uint4(cc[4], cc[5], cc[6], cc[7]);
}

// ------------------------- column finalize (2-thread-per-colpair) -------------
__global__ __launch_bounds__(256)
void k_colfinal() {
    __shared__ float rsm[32];
    int idx = blockIdx.x * 256 + threadIdx.x;   // < 65536
    int h   = idx & 1;
    int cp  = idx >> 1;                          // < 32768
    int mat = cp >> 14;
    int b   = (cp >> 9) & 31;
    int p   = cp & 511;

    const uint32_t* Sp = g_ScP + ((size_t)(mat*BSZ + b)*64 + (size_t)h*32)*512 + p;
    const uint32_t* Cp = g_CP  + ((size_t)(mat*BSZ + b)*64 + (size_t)h*32)*512 + p;

    float s0=0.f, s1=0.f, c0=0.f, c1=0.f;
#pragma unroll 8
    for (int sg = 0; sg < 32; sg++) {
        float a, bb;
        h2_to_f2(__ldcs(&Sp[(size_t)sg*512]), a, bb); s0 += a; s1 += bb;
        h2_to_f2(__ldcs(&Cp[(size_t)sg*512]), a, bb); c0 += a; c1 += bb;
    }
    s0 += __shfl_xor_sync(0xffffffffu, s0, 1);
    s1 += __shfl_xor_sync(0xffffffffu, s1, 1);
    c0 += __shfl_xor_sync(0xffffffffu, c0, 1);
    c1 += __shfl_xor_sync(0xffffffffu, c1, 1);

    float v = (h == 0) ? (__logf(s0)*c0 + __logf(s1)*c1) : 0.f;
    v = block_sum(v, rsm);
    if (threadIdx.x == 0) atomicAdd(&g_acc[4], (double)v);
}

// ------------------------- final combine -------------------------------------
__global__ void k_final(float* __restrict__ out) {
    int b = threadIdx.x;   // 32 threads
    float n1 = sqrtf(g_ssq1[b]);
    float n2 = sqrtf(g_ssq2[b]);
    float cosv = 1.f - g_dot[b] / (fmaxf(n1, 1e-8f) * fmaxf(n2, 1e-8f));
    cosv = wsum(cosv);
    if (b == 0) {
        double invBN = 1.0 / (double)(BSZ * NPT);
        double total = g_acc[0] * invBN
                     + g_acc[1] * invBN
                     + ENT_WT * invBN * (g_acc[2] + g_acc[4] - g_acc[3])
                     + (double)cosv / (double)BSZ;
        out[0] = (float)total;
    }
}

// ------------------------- launch --------------------------------------------
extern "C" void kernel_launch(void* const* d_in, const int* in_sizes, int n_in,
                              void* d_out, int out_size) {
    const float* P1 = (const float*)d_in[0];
    const float* P2 = (const float*)d_in[1];
    const float* A1 = (const float*)d_in[2];
    const float* A2 = (const float*)d_in[3];
    const float* sc = (const float*)d_in[4];
    const float* rt = (const float*)d_in[5];
    const float* tr = (const float*)d_in[6];
    float* out = (float*)d_out;

    k_setup<<<1, 64>>>(sc, rt, tr);
    k_pass1<<<dim3(BSZ, 128), 256>>>(A1, A2, P1, P2);
    k_rowfinal<<<TOT/256, 256>>>(P1, P2);
    k_chamfer<<<256, 512>>>();                     // 4th launch -> profiled
    k_pass2<<<1024, 256>>>();
    k_colfinal<<<256, 256>>>();
    k_final<<<1, 32>>>(out);
}

// round 17
// speedup vs baseline: 1.0928x; 1.0928x over previous
#include <cuda_runtime.h>
#include <cuda_fp16.h>
#include <cstdint>

#define BSZ 32
#define NPT 1024
#define NN (BSZ*NPT)      /* 32768 */
#define TOT (2*NN)        /* 65536 */

#define THRESH 0.1f
#define ENT_WT 1e-4

typedef unsigned long long ull;

// ------------------------- scratch (device globals; no mallocs) -------------
__device__ uint32_t g_E[2u*BSZ*NPT*256];     // 64 MiB: exp(A) as e4m3, 4 per u32
__device__ uint32_t g_ScP[2u*BSZ*64*512];    // 8 MiB: f16x2 column partial Sc
__device__ uint32_t g_CP [2u*BSZ*64*512];    // 8 MiB: f16x2 column partial C
__device__ float  g_Sr[TOT];
__device__ float  g_Tr[TOT];
__device__ float  g_invSr[TOT];
__device__ float4 g_U4[TOT];
__device__ float  g_ssq1[BSZ], g_ssq2[BSZ], g_dot[BSZ];
__device__ float  g_T12[BSZ*12], g_T21[BSZ*12];
__device__ float4 g_pin[TOT];   // mat0: p1in2, mat1: p2in1  (w = |p|^2)
__device__ float4 g_pto[TOT];   // mat0: p1to2, mat1: p2to1  (w = |p|^2)
__device__ double g_acc[6];     // 0 cham, 1 corr, 2 ent2, 3 entG, 4 colterm

// ------------------------- helpers ------------------------------------------
__device__ __forceinline__ float wsum(float v) {
#pragma unroll
    for (int o = 16; o; o >>= 1) v += __shfl_down_sync(0xffffffffu, v, o);
    return v;
}

__device__ __forceinline__ float block_sum(float v, float* sm) {
    int lane = threadIdx.x & 31, w = threadIdx.x >> 5;
    v = wsum(v);
    if (lane == 0) sm[w] = v;
    __syncthreads();
    int nw = (blockDim.x + 31) >> 5;
    v = (threadIdx.x < nw) ? sm[threadIdx.x] : 0.f;
    if (w == 0) v = wsum(v);
    return v;
}

// packed f32x2 helpers
__device__ __forceinline__ ull pk2(float a, float b) {
    ull r;
    asm("mov.b64 %0, {%1,%2};" : "=l"(r) : "f"(a), "f"(b));
    return r;
}
__device__ __forceinline__ void upk2(ull v, float& a, float& b) {
    asm("mov.b64 {%0,%1}, %2;" : "=f"(a), "=f"(b) : "l"(v));
}
__device__ __forceinline__ ull mul2(ull a, ull b) {
    ull d;
    asm("mul.rn.f32x2 %0, %1, %2;" : "=l"(d) : "l"(a), "l"(b));
    return d;
}
__device__ __forceinline__ ull add2(ull a, ull b) {
    ull d;
    asm("add.rn.f32x2 %0, %1, %2;" : "=l"(d) : "l"(a), "l"(b));
    return d;
}
__device__ __forceinline__ ull fma2(ull a, ull b, ull c) {
    ull d;
    asm("fma.rn.f32x2 %0, %1, %2, %3;" : "=l"(d) : "l"(a), "l"(b), "l"(c));
    return d;
}
__device__ __forceinline__ float ex2f(float x) {
    float r; asm("ex2.approx.f32 %0, %1;" : "=f"(r) : "f"(x)); return r;
}
__device__ __forceinline__ float sum2(ull v) {
    float a, b; upk2(v, a, b); return a + b;
}

// fp8 e4m3 pack/unpack
__device__ __forceinline__ uint32_t pack_e4m3x4(float f0, float f1, float f2, float f3) {
    uint32_t r;
    asm("{\n\t.reg .b16 lo, hi;\n\t"
        "cvt.rn.satfinite.e4m3x2.f32 lo, %2, %1;\n\t"
        "cvt.rn.satfinite.e4m3x2.f32 hi, %4, %3;\n\t"
        "mov.b32 %0, {lo, hi};\n\t}"
        : "=r"(r) : "f"(f0), "f"(f1), "f"(f2), "f"(f3));
    return r;
}
__device__ __forceinline__ void unpack_e4m3x4(uint32_t v, uint32_t& h01, uint32_t& h23) {
    asm("{\n\t.reg .b16 lo, hi;\n\t"
        "mov.b32 {lo, hi}, %2;\n\t"
        "cvt.rn.f16x2.e4m3x2 %0, lo;\n\t"
        "cvt.rn.f16x2.e4m3x2 %1, hi;\n\t}"
        : "=r"(h01), "=r"(h23) : "r"(v));
}
__device__ __forceinline__ uint32_t hadd2u(uint32_t a, uint32_t b) {
    uint32_t d; asm("add.rn.f16x2 %0, %1, %2;" : "=r"(d) : "r"(a), "r"(b)); return d;
}
__device__ __forceinline__ uint32_t hfma2u(uint32_t a, uint32_t b, uint32_t c) {
    uint32_t d; asm("fma.rn.f16x2 %0, %1, %2, %3;" : "=r"(d) : "r"(a), "r"(b), "r"(c)); return d;
}
__device__ __forceinline__ uint32_t bcast_h2(float w) {
    uint32_t d;
    asm("{\n\t.reg .b16 h;\n\tcvt.rn.f16.f32 h, %1;\n\tmov.b32 %0, {h, h};\n\t}"
        : "=r"(d) : "f"(w));
    return d;
}
__device__ __forceinline__ void h2_to_f2(uint32_t v, float& a, float& b) {
    asm("{\n\t.reg .b16 lo, hi;\n\tmov.b32 {lo, hi}, %2;\n\t"
        "cvt.f32.f16 %0, lo;\n\tcvt.f32.f16 %1, hi;\n\t}"
        : "=f"(a), "=f"(b) : "r"(v));
}

// ------------------------- setup: init + pose (one launch) --------------------
__global__ void k_setup(const float* __restrict__ scale,
                        const float* __restrict__ rot,
                        const float* __restrict__ trans) {
    int i = threadIdx.x;   // 64 threads
    if (i >= 32 && i < 38) g_acc[i - 32] = 0.0;
    if (i >= BSZ) return;
    g_ssq1[i] = 0.f; g_ssq2[i] = 0.f; g_dot[i] = 0.f;

    int b = i;
    float s = scale[b];
    float m[9];
#pragma unroll
    for (int k = 0; k < 9; k++) m[k] = s * rot[b*9 + k];
    float t0 = trans[b*3+0], t1 = trans[b*3+1], t2 = trans[b*3+2];

    float* T = g_T12 + b*12;
    T[0]=m[0]; T[1]=m[1]; T[2]=m[2];  T[3]=t0;
    T[4]=m[3]; T[5]=m[4]; T[6]=m[5];  T[7]=t1;
    T[8]=m[6]; T[9]=m[7]; T[10]=m[8]; T[11]=t2;

    float c00=(m[4]*m[8]-m[5]*m[7]), c01=(m[2]*m[7]-m[1]*m[8]), c02=(m[1]*m[5]-m[2]*m[4]);
    float c10=(m[5]*m[6]-m[3]*m[8]), c11=(m[0]*m[8]-m[2]*m[6]), c12=(m[2]*m[3]-m[0]*m[5]);
    float c20=(m[3]*m[7]-m[4]*m[6]), c21=(m[1]*m[6]-m[0]*m[7]), c22=(m[0]*m[4]-m[1]*m[3]);
    float det = m[0]*c00 + m[1]*c10 + m[2]*c20;
    float id = 1.f/det;
    float i00=c00*id,i01=c01*id,i02=c02*id;
    float i10=c10*id,i11=c11*id,i12=c12*id;
    float i20=c20*id,i21=c21*id,i22=c22*id;
    float u0 = -(i00*t0 + i01*t1 + i02*t2);
    float u1 = -(i10*t0 + i11*t1 + i12*t2);
    float u2 = -(i20*t0 + i21*t1 + i22*t2);
    float* V = g_T21 + b*12;
    V[0]=i00; V[1]=i01; V[2]=i02;  V[3]=u0;
    V[4]=i10; V[5]=i11; V[6]=i12;  V[7]=u1;
    V[8]=i20; V[9]=i21; V[10]=i22; V[11]=u2;
}

// ------------------------- pass 1 (round-10 proven: packed f32x2, 1 row/warp) -
__global__ __launch_bounds__(256, 4)
void k_pass1(const float* __restrict__ A1, const float* __restrict__ A2,
             const float* __restrict__ P1, const float* __restrict__ P2) {
    __shared__ ull s1x[NPT/2], s1y[NPT/2], s1z[NPT/2];
    __shared__ ull s2x[NPT/2], s2y[NPT/2], s2z[NPT/2];
    __shared__ float rsm[32];

    const int b  = blockIdx.x;
    const int rb = blockIdx.y;
    const int tid = threadIdx.x;
    const int warp = tid >> 5, lane = tid & 31;

    const float* P1g = P1 + (size_t)b*NPT*3;
    const float* P2g = P2 + (size_t)b*NPT*3;
    for (int i = tid; i < NPT/2; i += 256) {
        const float* c1 = P1g + 6*i;
        s1x[i] = pk2(c1[0], c1[3]);
        s1y[i] = pk2(c1[1], c1[4]);
        s1z[i] = pk2(c1[2], c1[5]);
        const float* c2 = P2g + 6*i;
        s2x[i] = pk2(c2[0], c2[3]);
        s2y[i] = pk2(c2[1], c2[4]);
        s2z[i] = pk2(c2[2], c2[5]);
    }
    __syncthreads();

    const int row = rb*8 + warp;
    const float* A1r = A1 + ((size_t)b << 20) + ((size_t)row << 10);
    const float* A2r = A2 + ((size_t)b << 20) + ((size_t)row << 10);
    uint32_t* E1r = g_E + ((size_t)b << 18) + row*256;
    uint32_t* E2r = g_E + ((size_t)(BSZ + b) << 18) + row*256;

    const ull L2E = pk2(1.4426950408889634f, 1.4426950408889634f);

    ull sP1=0, tP1=0, uxP1=0, uyP1=0, uzP1=0;
    ull sP2=0, tP2=0, uxP2=0, uyP2=0, uzP2=0;
    ull ssP1=0, ssP2=0, dpP=0;

#pragma unroll
    for (int c = 0; c < 8; c++) {
        const int col = c*128 + lane*4;
        const float4 a1 = __ldcs((const float4*)&A1r[col]);
        const float4 a2 = __ldcs((const float4*)&A2r[col]);
        const ulonglong2 q2x = *(const ulonglong2*)&s2x[col >> 1];
        const ulonglong2 q2y = *(const ulonglong2*)&s2y[col >> 1];
        const ulonglong2 q2z = *(const ulonglong2*)&s2z[col >> 1];
        const ulonglong2 q1x = *(const ulonglong2*)&s1x[col >> 1];
        const ulonglong2 q1y = *(const ulonglong2*)&s1y[col >> 1];
        const ulonglong2 q1z = *(const ulonglong2*)&s1z[col >> 1];

        {
            ull a01 = pk2(a1.x, a1.y), a23 = pk2(a1.z, a1.w);
            ull x01 = mul2(a01, L2E),  x23 = mul2(a23, L2E);
            float f0, f1, f2, f3;
            upk2(x01, f0, f1); upk2(x23, f2, f3);
            float e0 = ex2f(f0), e1 = ex2f(f1), e2 = ex2f(f2), e3 = ex2f(f3);
            ull e01 = pk2(e0, e1), e23 = pk2(e2, e3);
            sP1 = add2(sP1, e01);      sP1 = add2(sP1, e23);
            tP1 = fma2(e01, a01, tP1); tP1 = fma2(e23, a23, tP1);
            uxP1 = fma2(e01, q2x.x, uxP1); uxP1 = fma2(e23, q2x.y, uxP1);
            uyP1 = fma2(e01, q2y.x, uyP1); uyP1 = fma2(e23, q2y.y, uyP1);
            uzP1 = fma2(e01, q2z.x, uzP1); uzP1 = fma2(e23, q2z.y, uzP1);
            ssP1 = fma2(a01, a01, ssP1);   ssP1 = fma2(a23, a23, ssP1);
            E1r[col >> 2] = pack_e4m3x4(e0, e1, e2, e3);

            ull b01 = pk2(a2.x, a2.y), b23 = pk2(a2.z, a2.w);
            dpP = fma2(a01, b01, dpP); dpP = fma2(a23, b23, dpP);
            ssP2 = fma2(b01, b01, ssP2);   ssP2 = fma2(b23, b23, ssP2);

            ull y01 = mul2(b01, L2E), y23 = mul2(b23, L2E);
            float g0, g1, g2, g3;
            upk2(y01, g0, g1); upk2(y23, g2, g3);
            float h0 = ex2f(g0), h1 = ex2f(g1), h2 = ex2f(g2), h3 = ex2f(g3);
            ull h01 = pk2(h0, h1), h23 = pk2(h2, h3);
            sP2 = add2(sP2, h01);      sP2 = add2(sP2, h23);
            tP2 = fma2(h01, b01, tP2); tP2 = fma2(h23, b23, tP2);
            uxP2 = fma2(h01, q1x.x, uxP2); uxP2 = fma2(h23, q1x.y, uxP2);
            uyP2 = fma2(h01, q1y.x, uyP2); uyP2 = fma2(h23, q1y.y, uyP2);
            uzP2 = fma2(h01, q1z.x, uzP2); uzP2 = fma2(h23, q1z.y, uzP2);
            E2r[col >> 2] = pack_e4m3x4(h0, h1, h2, h3);
        }
    }

    float s1 = wsum(sum2(sP1)),  t1 = wsum(sum2(tP1));
    float ux1 = wsum(sum2(uxP1)), uy1 = wsum(sum2(uyP1)), uz1 = wsum(sum2(uzP1));
    float s2v = wsum(sum2(sP2)),  t2v = wsum(sum2(tP2));
    float ux2 = wsum(sum2(uxP2)), uy2 = wsum(sum2(uyP2)), uz2 = wsum(sum2(uzP2));
    if (lane == 0) {
        size_t i1 = (size_t)b*NPT + row;
        size_t i2 = (size_t)NN + i1;
        g_Sr[i1] = s1; g_Tr[i1] = t1; g_invSr[i1] = 1.f/s1;
        g_U4[i1] = make_float4(ux1, uy1, uz1, 0.f);
        g_Sr[i2] = s2v; g_Tr[i2] = t2v; g_invSr[i2] = 1.f/s2v;
        g_U4[i2] = make_float4(ux2, uy2, uz2, 0.f);
    }

    float v = block_sum(sum2(ssP1), rsm);
    if (tid == 0) atomicAdd(&g_ssq1[b], v);
    __syncthreads();
    v = block_sum(sum2(ssP2), rsm);
    if (tid == 0) atomicAdd(&g_ssq2[b], v);
    __syncthreads();
    v = block_sum(sum2(dpP), rsm);
    if (tid == 0) atomicAdd(&g_dot[b], v);
}

// ------------------------- merged A: pass2 (bx<1024) + rowfinal (bx>=1024) ----
__device__ void d_pass2(int bx) {
    __shared__ float isr[64];
    const int chunk = bx & 15, b = (bx >> 4) & 31, mat = bx >> 9;
    const int tid = threadIdx.x;
    const int sub = tid >> 6, ct = tid & 63;

    if (tid < 64)
        isr[tid] = g_invSr[(size_t)(mat*BSZ + b)*NPT + chunk*64 + tid];
    __syncthreads();

    const int row0 = chunk*64 + sub*16;
    const uint4* Ep = (const uint4*)(g_E + ((size_t)(mat*BSZ + b) << 18) + row0*256) + ct;

    uint32_t sc[8], cc[8];
#pragma unroll
    for (int k = 0; k < 8; k++) { sc[k] = 0u; cc[k] = 0u; }

#pragma unroll 8
    for (int r = 0; r < 16; r++) {
        uint4 v = __ldcs(&Ep[(size_t)r*64]);
        uint32_t w2 = bcast_h2(isr[sub*16 + r]);
        uint32_t h0, h1;
        unpack_e4m3x4(v.x, h0, h1);
        sc[0]=hadd2u(sc[0],h0); cc[0]=hfma2u(h0,w2,cc[0]);
        sc[1]=hadd2u(sc[1],h1); cc[1]=hfma2u(h1,w2,cc[1]);
        unpack_e4m3x4(v.y, h0, h1);
        sc[2]=hadd2u(sc[2],h0); cc[2]=hfma2u(h0,w2,cc[2]);
        sc[3]=hadd2u(sc[3],h1); cc[3]=hfma2u(h1,w2,cc[3]);
        unpack_e4m3x4(v.z, h0, h1);
        sc[4]=hadd2u(sc[4],h0); cc[4]=hfma2u(h0,w2,cc[4]);
        sc[5]=hadd2u(sc[5],h1); cc[5]=hfma2u(h1,w2,cc[5]);
        unpack_e4m3x4(v.w, h0, h1);
        sc[6]=hadd2u(sc[6],h0); cc[6]=hfma2u(h0,w2,cc[6]);
        sc[7]=hadd2u(sc[7],h1); cc[7]=hfma2u(h1,w2,cc[7]);
    }

    const size_t o = (((size_t)(mat*BSZ + b)*64) + (size_t)(chunk*4 + sub))*512 + ct*8;
    *(uint4*)&g_ScP[o]     = make_uint4(sc[0], sc[1], sc[2], sc[3]);
    *(uint4*)&g_ScP[o + 4] = make_uint4(sc[4], sc[5], sc[6], sc[7]);
    *(uint4*)&g_CP[o]      = make_uint4(cc[0], cc[1], cc[2], cc[3]);
    *(uint4*)&g_CP[o + 4]  = make_uint4(cc[4], cc[5], cc[6], cc[7]);
}

__device__ void d_rowfinal(int bx, const float* __restrict__ P1,
                           const float* __restrict__ P2) {
    __shared__ float rsm[32];
    int idx = bx * 256 + threadIdx.x;   // < 65536
    int mat = idx >> 15;
    int b   = (idx >> 10) & 31;
    int n   = idx & 1023;

    float sr  = g_Sr[idx];
    float isr = 1.f / sr;
    float gq  = g_Tr[idx] * isr;
    float e2p = __logf(sr) - gq;

    float4 u = g_U4[idx];
    float px = u.x*isr, py = u.y*isr, pz = u.z*isr;
    g_pin[idx] = make_float4(px, py, pz, px*px+py*py+pz*pz);

    const float* pts = mat ? P2 : P1;
    const float* T   = (mat ? g_T21 : g_T12) + b*12;
    float x0 = pts[((size_t)b*NPT+n)*3+0];
    float x1 = pts[((size_t)b*NPT+n)*3+1];
    float x2 = pts[((size_t)b*NPT+n)*3+2];
    float y0 = T[0]*x0 + T[1]*x1 + T[2]*x2 + T[3];
    float y1 = T[4]*x0 + T[5]*x1 + T[6]*x2 + T[7];
    float y2 = T[8]*x0 + T[9]*x1 + T[10]*x2 + T[11];
    g_pto[idx] = make_float4(y0, y1, y2, y0*y0+y1*y1+y2*y2);

#define HUBER(d) ((d) > THRESH ? (d) - 0.5f*THRESH : (d)*(d)*(0.5f/THRESH))
    float d0 = fabsf(px-y0), d1 = fabsf(py-y1), d2 = fabsf(pz-y2);
    float corr = HUBER(d0) + HUBER(d1) + HUBER(d2);
#undef HUBER

    float v = block_sum(e2p, rsm);
    if (threadIdx.x == 0) atomicAdd(&g_acc[2], (double)v);
    __syncthreads();
    v = block_sum(gq, rsm);
    if (threadIdx.x == 0) atomicAdd(&g_acc[3], (double)v);
    __syncthreads();
    v = block_sum(corr, rsm);
    if (threadIdx.x == 0) atomicAdd(&g_acc[1], (double)v);
}

__global__ __launch_bounds__(256)
void k_mergedA(const float* __restrict__ P1, const float* __restrict__ P2) {
    int bx = blockIdx.x;   // 0..1279
    if (bx < 1024) d_pass2(bx);
    else           d_rowfinal(bx - 1024, P1, P2);
}

// ------------------------- merged B: chamfer (bx<256) + colfinal --------------
// chamfer (r14 proven): 512 threads, g = tid>>7 y-quarter, t = tid&127, 4 x-pts.
__device__ void d_chamfer(int bx) {
    __shared__ ulonglong2 sYA[NPT/2];   // (x-pair, y-pair)
    __shared__ ulonglong2 sYB[NPT/2];   // (z-pair, w-pair)
    __shared__ float pm[4*512];         // [k][g*128+t] partial minima (8 KB)
    __shared__ float rsm[32];
    int half = bx & 1; int b = (bx >> 1) & 31; int dir = (bx >> 6) & 1; int prob = bx >> 7;
    size_t base = (size_t)(prob*BSZ + b) * NPT;
    const float4* X = dir ? (g_pin + base) : (g_pto + base);
    const float4* Y = dir ? (g_pto + base) : (g_pin + base);
    int tid = threadIdx.x;
    int g = tid >> 7, t = tid & 127;

    for (int i = tid; i < NPT/2; i += 512) {
        float4 y0 = Y[2*i], y1 = Y[2*i+1];
        sYA[i] = make_ulonglong2(pk2(y0.x, y1.x), pk2(y0.y, y1.y));
        sYB[i] = make_ulonglong2(pk2(y0.z, y1.z), pk2(y0.w, y1.w));
    }
    __syncthreads();

    const float4 x0 = X[half*512 + t];
    const float4 x1 = X[half*512 + t + 128];
    const float4 x2 = X[half*512 + t + 256];
    const float4 x3 = X[half*512 + t + 384];
    ull a0x = pk2(-2.f*x0.x, -2.f*x0.x), a0y = pk2(-2.f*x0.y, -2.f*x0.y), a0z = pk2(-2.f*x0.z, -2.f*x0.z);
    ull a1x = pk2(-2.f*x1.x, -2.f*x1.x), a1y = pk2(-2.f*x1.y, -2.f*x1.y), a1z = pk2(-2.f*x1.z, -2.f*x1.z);
    ull a2x = pk2(-2.f*x2.x, -2.f*x2.x), a2y = pk2(-2.f*x2.y, -2.f*x2.y), a2z = pk2(-2.f*x2.z, -2.f*x2.z);
    ull a3x = pk2(-2.f*x3.x, -2.f*x3.x), a3y = pk2(-2.f*x3.y, -2.f*x3.y), a3z = pk2(-2.f*x3.z, -2.f*x3.z);

    float mn0 = 1e30f, mn1 = 1e30f, mn2 = 1e30f, mn3 = 1e30f;
    const int m0 = g*128;
#pragma unroll 4
    for (int m = m0; m < m0 + 128; m++) {
        ulonglong2 A = sYA[m];
        ulonglong2 B = sYB[m];
        ull v; float lo, hi;
        v = fma2(a0x, A.x, B.y); v = fma2(a0y, A.y, v); v = fma2(a0z, B.x, v);
        upk2(v, lo, hi); mn0 = fminf(mn0, fminf(lo, hi));
        v = fma2(a1x, A.x, B.y); v = fma2(a1y, A.y, v); v = fma2(a1z, B.x, v);
        upk2(v, lo, hi); mn1 = fminf(mn1, fminf(lo, hi));
        v = fma2(a2x, A.x, B.y); v = fma2(a2y, A.y, v); v = fma2(a2z, B.x, v);
        upk2(v, lo, hi); mn2 = fminf(mn2, fminf(lo, hi));
        v = fma2(a3x, A.x, B.y); v = fma2(a3y, A.y, v); v = fma2(a3z, B.x, v);
        upk2(v, lo, hi); mn3 = fminf(mn3, fminf(lo, hi));
    }
    pm[0*512 + g*128 + t] = mn0;
    pm[1*512 + g*128 + t] = mn1;
    pm[2*512 + g*128 + t] = mn2;
    pm[3*512 + g*128 + t] = mn3;
    __syncthreads();

    float dsum = 0.f;
    if (g == 0) {
        float f0 = fminf(fminf(pm[0*512 + t],       pm[0*512 + 128 + t]),
                         fminf(pm[0*512 + 256 + t], pm[0*512 + 384 + t]));
        float f1 = fminf(fminf(pm[1*512 + t],       pm[1*512 + 128 + t]),
                         fminf(pm[1*512 + 256 + t], pm[1*512 + 384 + t]));
        float f2 = fminf(fminf(pm[2*512 + t],       pm[2*512 + 128 + t]),
                         fminf(pm[2*512 + 256 + t], pm[2*512 + 384 + t]));
        float f3 = fminf(fminf(pm[3*512 + t],       pm[3*512 + 128 + t]),
                         fminf(pm[3*512 + 256 + t], pm[3*512 + 384 + t]));
        dsum = fmaxf(x0.w + f0, 0.f) + fmaxf(x1.w + f1, 0.f)
             + fmaxf(x2.w + f2, 0.f) + fmaxf(x3.w + f3, 0.f);
    }
    float v = block_sum(dsum, rsm);
    if (tid == 0) atomicAdd(&g_acc[0], (double)v);
}

// colfinal with 512-thread blocks: 128 blocks cover 65536 items.
__device__ void d_colfinal(int bx) {
    __shared__ float rsm[32];
    int idx = bx * 512 + threadIdx.x;   // < 65536
    int h   = idx & 1;
    int cp  = idx >> 1;                  // < 32768
    int mat = cp >> 14;
    int b   = (cp >> 9) & 31;
    int p   = cp & 511;

    const uint32_t* Sp = g_ScP + ((size_t)(mat*BSZ + b)*64 + (size_t)h*32)*512 + p;
    const uint32_t* Cp = g_CP  + ((size_t)(mat*BSZ + b)*64 + (size_t)h*32)*512 + p;

    float s0=0.f, s1=0.f, c0=0.f, c1=0.f;
#pragma unroll 8
    for (int sg = 0; sg < 32; sg++) {
        float a, bb;
        h2_to_f2(__ldcs(&Sp[(size_t)sg*512]), a, bb); s0 += a; s1 += bb;
        h2_to_f2(__ldcs(&Cp[(size_t)sg*512]), a, bb); c0 += a; c1 += bb;
    }
    s0 += __shfl_xor_sync(0xffffffffu, s0, 1);
    s1 += __shfl_xor_sync(0xffffffffu, s1, 1);
    c0 += __shfl_xor_sync(0xffffffffu, c0, 1);
    c1 += __shfl_xor_sync(0xffffffffu, c1, 1);

    float v = (h == 0) ? (__logf(s0)*c0 + __logf(s1)*c1) : 0.f;
    v = block_sum(v, rsm);
    if (threadIdx.x == 0) atomicAdd(&g_acc[4], (double)v);
}

__global__ __launch_bounds__(512)
void k_mergedB() {
    int bx = blockIdx.x;    // 0..383
    if (bx < 256) d_chamfer(bx);
    else          d_colfinal(bx - 256);
}

// ------------------------- final combine -------------------------------------
__global__ void k_final(float* __restrict__ out) {
    int b = threadIdx.x;   // 32 threads
    float n1 = sqrtf(g_ssq1[b]);
    float n2 = sqrtf(g_ssq2[b]);
    float cosv = 1.f - g_dot[b] / (fmaxf(n1, 1e-8f) * fmaxf(n2, 1e-8f));
    cosv = wsum(cosv);
    if (b == 0) {
        double invBN = 1.0 / (double)(BSZ * NPT);
        double total = g_acc[0] * invBN
                     + g_acc[1] * invBN
                     + ENT_WT * invBN * (g_acc[2] + g_acc[4] - g_acc[3])
                     + (double)cosv / (double)BSZ;
        out[0] = (float)total;
    }
}

// ------------------------- launch --------------------------------------------
extern "C" void kernel_launch(void* const* d_in, const int* in_sizes, int n_in,
                              void* d_out, int out_size) {
    const float* P1 = (const float*)d_in[0];
    const float* P2 = (const float*)d_in[1];
    const float* A1 = (const float*)d_in[2];
    const float* A2 = (const float*)d_in[3];
    const float* sc = (const float*)d_in[4];
    const float* rt = (const float*)d_in[5];
    const float* tr = (const float*)d_in[6];
    float* out = (float*)d_out;

    k_setup<<<1, 64>>>(sc, rt, tr);
    k_pass1<<<dim3(BSZ, 128), 256>>>(A1, A2, P1, P2);
    k_mergedA<<<1280, 256>>>(P1, P2);
    k_mergedB<<<384, 512>>>();                     // 4th launch -> profiled
    k_final<<<1, 32>>>(out);
}